// round 16
// baseline (speedup 1.0000x reference)
#include <cuda_runtime.h>
#include <cuda_fp16.h>
#include <math.h>
#include <stdint.h>

#define BB 4
#define LL 4096
#define TT (BB*LL)
#define DM 1024
#define HH 16
#define DH 64
#define MF 128
#define TWO_M 256
#define KV_SPLIT 16
#define LSPLIT (LL/KV_SPLIT)   // 256

#define INV_SQRT_DH 0.125f
#define INV_SQRT_MF 0.08838834764831843f

__device__ float g_q[TT*DM];
__device__ float g_k[TT*DM];
__device__ float g_v[TT*DM];
__device__ __half g_xh[TT*DM];
__device__ __half g_ath[TT*DM];
__device__ __half g_wh[4*DM*DM];
__device__ float g_kvp[(size_t)KV_SPLIT*BB*HH*TWO_M*DH];
__device__ float g_kv[(size_t)BB*HH*TWO_M*DH];

__device__ __forceinline__ float tf32r(float x) {
    uint32_t u;
    asm("cvt.rna.tf32.f32 %0, %1;" : "=r"(u) : "f"(x));
    return __uint_as_float(u);
}

__device__ __forceinline__ uint32_t h2u(__half2 h) {
    return *reinterpret_cast<uint32_t*>(&h);
}

__device__ __forceinline__ void mma_tf32(float* d, const uint32_t* a, const uint32_t* b) {
    asm volatile(
        "mma.sync.aligned.m16n8k8.row.col.f32.tf32.tf32.f32 "
        "{%0,%1,%2,%3}, {%4,%5,%6,%7}, {%8,%9}, {%0,%1,%2,%3};\n"
        : "+f"(d[0]), "+f"(d[1]), "+f"(d[2]), "+f"(d[3])
        : "r"(a[0]), "r"(a[1]), "r"(a[2]), "r"(a[3]), "r"(b[0]), "r"(b[1]));
}

__device__ __forceinline__ void mma_f16(float* d, const uint32_t* a, const uint32_t* b) {
    asm volatile(
        "mma.sync.aligned.m16n8k16.row.col.f32.f16.f16.f32 "
        "{%0,%1,%2,%3}, {%4,%5,%6,%7}, {%8,%9}, {%0,%1,%2,%3};\n"
        : "+f"(d[0]), "+f"(d[1]), "+f"(d[2]), "+f"(d[3])
        : "r"(a[0]), "r"(a[1]), "r"(a[2]), "r"(a[3]), "r"(b[0]), "r"(b[1]));
}

__device__ __forceinline__ uint32_t smaddr(const void* p) {
    return (uint32_t)__cvta_generic_to_shared(p);
}

__device__ __forceinline__ void ldsm4(uint32_t* r, uint32_t a) {
    asm volatile("ldmatrix.sync.aligned.m8n8.x4.shared.b16 {%0,%1,%2,%3}, [%4];"
                 : "=r"(r[0]), "=r"(r[1]), "=r"(r[2]), "=r"(r[3]) : "r"(a));
}

// float-unit patterns (tf32 kernels)
#define AOFF(lane, STR) (((((lane) >> 3) & 1) * 8 + ((lane) & 7)) * (STR) + ((lane) >> 4) * 4)
#define BOFF(lane, STR) ((((lane) >> 4) * 8 + ((lane) & 7)) * (STR) + (((lane) >> 3) & 1) * 4)
// half-unit patterns (f16 GEMM), column groups of 8 halves
#define AOFFH(lane, STR) (((((lane) >> 3) & 1) * 8 + ((lane) & 7)) * (STR) + ((lane) >> 4) * 8)
#define BOFFH(lane, STR) ((((lane) >> 4) * 8 + ((lane) & 7)) * (STR) + (((lane) >> 3) & 1) * 8)

// ---------------------------------------------------------------------------
// prep: fp32 -> fp16 conversions
// ---------------------------------------------------------------------------
__global__ void cvt_x_h(const float4* __restrict__ src, uint2* __restrict__ dst, int n8)
{
    int i = blockIdx.x * 256 + threadIdx.x;
    if (i >= n8) return;
    float4 a = src[i * 2], b = src[i * 2 + 1];
    uint2 o, o2;
    o.x  = h2u(__floats2half2_rn(a.x, a.y));
    o.y  = h2u(__floats2half2_rn(a.z, a.w));
    o2.x = h2u(__floats2half2_rn(b.x, b.y));
    o2.y = h2u(__floats2half2_rn(b.z, b.w));
    dst[i * 2] = o;
    dst[i * 2 + 1] = o2;
}

__global__ void cvt_w_h(const float4* __restrict__ wq, const float4* __restrict__ wk,
                        const float4* __restrict__ wv, const float4* __restrict__ wo,
                        uint2* __restrict__ dst)
{
    const int WN4 = DM * DM / 4;
    int i = blockIdx.x * 256 + threadIdx.x;
    if (i >= 4 * WN4) return;
    int sel = i / WN4, off = i - sel * WN4;
    const float4* src = (sel == 0) ? wq : (sel == 1) ? wk : (sel == 2) ? wv : wo;
    float4 v = src[off];
    uint2 o;
    o.x = h2u(__floats2half2_rn(v.x, v.y));
    o.y = h2u(__floats2half2_rn(v.z, v.w));
    dst[i] = o;
}

// ---------------------------------------------------------------------------
// f16 GEMM body: C[128,128 tile] = A[M,1024] * W[N,1024]^T + bias (fp32 acc)
// cp.async 3-stage, ldmatrix f16 fragments, m16n8k16. 256 threads, 2 CTA/SM.
// HSTR=40 halves (80B) keeps every ldmatrix row pointer 16B-aligned.
// ---------------------------------------------------------------------------
#define GS 3
#define HSTR 40
#define HSTAGE (128*HSTR)                 // 5120 halves per operand per stage
#define GSMEMH (2*GS*HSTAGE*2)            // 61440 bytes

__device__ __forceinline__ void gemm_body_h(
    const __half* __restrict__ A, const __half* __restrict__ W,
    const float* __restrict__ bias, float* __restrict__ C)
{
    extern __shared__ __half sh[];
    __half* As = sh;
    __half* Ws = sh + GS * HSTAGE;

    const int tid = threadIdx.x;
    const int bm = blockIdx.y * 128;
    const int bn = blockIdx.x * 128;
    const int warp = tid >> 5, lane = tid & 31;
    const int wm = (warp & 1) * 64;
    const int wn = (warp >> 1) * 32;
    const int g = lane >> 2, c = lane & 3;
    const int aoff = AOFFH(lane, HSTR);
    const int boff = BOFFH(lane, HSTR);

    float d[4][4][4];
#pragma unroll
    for (int mt = 0; mt < 4; mt++)
#pragma unroll
        for (int nt = 0; nt < 4; nt++)
#pragma unroll
            for (int r = 0; r < 4; r++) d[mt][nt][r] = 0.f;

    auto issue = [&](int st, int k0) {
#pragma unroll
        for (int j = 0; j < 4; j++) {
            int id = tid + j * 256;        // 0..1023
            if (id < 512) {
                int row = id >> 2, c16 = (id & 3) * 8;
                asm volatile("cp.async.cg.shared.global [%0], [%1], 16;\n"
                             :: "r"(smaddr(&As[st * HSTAGE + row * HSTR + c16])),
                                "l"(A + (size_t)(bm + row) * DM + k0 + c16));
            } else {
                int id2 = id - 512;
                int row = id2 >> 2, c16 = (id2 & 3) * 8;
                asm volatile("cp.async.cg.shared.global [%0], [%1], 16;\n"
                             :: "r"(smaddr(&Ws[st * HSTAGE + row * HSTR + c16])),
                                "l"(W + (size_t)(bn + row) * DM + k0 + c16));
            }
        }
    };

    issue(0, 0);  asm volatile("cp.async.commit_group;\n");
    issue(1, 32); asm volatile("cp.async.commit_group;\n");

    const int NIT = DM / 32;
    for (int i = 0; i < NIT; i++) {
        asm volatile("cp.async.wait_group 1;\n");
        __syncthreads();
        if (i + 2 < NIT) issue((i + 2) % GS, (i + 2) * 32);
        asm volatile("cp.async.commit_group;\n");

        const __half* Ab = As + (i % GS) * HSTAGE;
        const __half* Wb = Ws + (i % GS) * HSTAGE;
#pragma unroll
        for (int ks = 0; ks < 2; ks++) {
            const int kb = ks * 16;
            uint32_t a[4][4], bq2[2][4];
#pragma unroll
            for (int mt = 0; mt < 4; mt++)
                ldsm4(a[mt], smaddr(Ab + (wm + mt * 16) * HSTR + kb + aoff));
            ldsm4(bq2[0], smaddr(Wb + wn * HSTR + kb + boff));
            ldsm4(bq2[1], smaddr(Wb + (wn + 16) * HSTR + kb + boff));
#pragma unroll
            for (int mt = 0; mt < 4; mt++)
#pragma unroll
                for (int nt = 0; nt < 4; nt++)
                    mma_f16(d[mt][nt], a[mt], &bq2[nt >> 1][(nt & 1) * 2]);
        }
    }

#pragma unroll
    for (int nt = 0; nt < 4; nt++) {
        int col = bn + wn + nt * 8 + 2 * c;
        float b0 = bias[col], b1 = bias[col + 1];
#pragma unroll
        for (int mt = 0; mt < 4; mt++) {
            int row = bm + wm + mt * 16 + g;
            *(float2*)(C + (size_t)row * DM + col) =
                make_float2(d[mt][nt][0] + b0, d[mt][nt][1] + b1);
            *(float2*)(C + (size_t)(row + 8) * DM + col) =
                make_float2(d[mt][nt][2] + b0, d[mt][nt][3] + b1);
        }
    }
}

__global__ __launch_bounds__(256, 2) void kv_gemm_h(
    const __half* __restrict__ A, const __half* __restrict__ Wh,
    const float* __restrict__ bk, const float* __restrict__ bv,
    float* __restrict__ k, float* __restrict__ v)
{
    int z = blockIdx.z;
    const __half* W = Wh + (size_t)(z + 1) * DM * DM;
    const float* bias = (z == 0) ? bk : bv;
    float* C = (z == 0) ? k : v;
    gemm_body_h(A, W, bias, C);
}

__global__ __launch_bounds__(256, 2) void gemm_one_h(
    const __half* __restrict__ A, const __half* __restrict__ W,
    const float* __restrict__ bias, float* __restrict__ C)
{
    gemm_body_h(A, W, bias, C);
}

// ---------------------------------------------------------------------------
// feat_kv (unchanged from R13): 32-token chunks, 2 CTAs/SM.
// ---------------------------------------------------------------------------
#define FSTR 68
#define TSTR 36
#define FEAT_SMEM ((128*FSTR + 32*FSTR + 64*TSTR + 256*TSTR) * 4)

__global__ __launch_bounds__(512, 2) void feat_kv(
    const float* __restrict__ Kmat, const float* __restrict__ Vmat,
    const float* __restrict__ proj, float* __restrict__ kvp)
{
    extern __shared__ float sm[];
    float* projT = sm;
    float* ksh   = projT + 128 * FSTR;
    float* vts   = ksh   + 32 * FSTR;
    float* kpt   = vts   + 64 * TSTR;

    const int split = blockIdx.x, h = blockIdx.y, b = blockIdx.z;
    const int tid = threadIdx.x;
    const int warp = tid >> 5, lane = tid & 31;
    const int g = lane >> 2, c = lane & 3;
    const int aoffF = AOFF(lane, FSTR);
    const int boffF = BOFF(lane, FSTR);
    const int aoffT = AOFF(lane, TSTR);
    const int boffT = BOFF(lane, TSTR);

    for (int it = tid; it < 2048; it += 512) {
        int d = it >> 5;
        int m4 = (it & 31) * 4;
        float4 pv = *(const float4*)(proj + d * MF + m4);
        projT[(m4 + 0) * FSTR + d] = tf32r(pv.x);
        projT[(m4 + 1) * FSTR + d] = tf32r(pv.y);
        projT[(m4 + 2) * FSTR + d] = tf32r(pv.z);
        projT[(m4 + 3) * FSTR + d] = tf32r(pv.w);
    }

    const int wtokA = (warp & 1) * 16, wmA = (warp >> 1) * 16;
    const int mB0 = (warp & 7) * 32, dB0 = (warp >> 3) * 32;
    const int l0 = split * LSPLIT;

    float kvacc[2][4][4];
#pragma unroll
    for (int mi = 0; mi < 2; mi++)
#pragma unroll
        for (int nj = 0; nj < 4; nj++)
#pragma unroll
            for (int r = 0; r < 4; r++) kvacc[mi][nj][r] = 0.f;

    for (int ch = 0; ch < LSPLIT; ch += 32) {
        __syncthreads();
        {
            int it = tid;
            int t = it >> 4;
            int d4 = (it & 15) * 4;
            size_t row = (size_t)(b * LL + l0 + ch + t) * DM + h * DH + d4;
            float4 kvv = *(const float4*)(Kmat + row);
            *(float4*)&ksh[t * FSTR + d4] = make_float4(
                tf32r(kvv.x), tf32r(kvv.y), tf32r(kvv.z), tf32r(kvv.w));
            float4 vv = *(const float4*)(Vmat + row);
            vts[(d4 + 0) * TSTR + t] = tf32r(vv.x);
            vts[(d4 + 1) * TSTR + t] = tf32r(vv.y);
            vts[(d4 + 2) * TSTR + t] = tf32r(vv.z);
            vts[(d4 + 3) * TSTR + t] = tf32r(vv.w);
        }
        __syncthreads();

        float pacc[2][4];
#pragma unroll
        for (int nj = 0; nj < 2; nj++)
#pragma unroll
            for (int r = 0; r < 4; r++) pacc[nj][r] = 0.f;

#pragma unroll
        for (int ks = 0; ks < 8; ks++) {
            const int kb = ks * 8;
            uint32_t ah[4], bfr[4];
            ldsm4(ah, smaddr(ksh + wtokA * FSTR + kb + aoffF));
            ldsm4(bfr, smaddr(projT + wmA * FSTR + kb + boffF));
#pragma unroll
            for (int nj = 0; nj < 2; nj++)
                mma_tf32(pacc[nj], ah, &bfr[nj * 2]);
        }

#pragma unroll
        for (int nj = 0; nj < 2; nj++)
#pragma unroll
            for (int r = 0; r < 4; r++) {
                int tok = wtokA + g + (r >> 1) * 8;
                int m = wmA + nj * 8 + 2 * c + (r & 1);
                float p = pacc[nj][r] * INV_SQRT_DH;
                kpt[m * TSTR + tok] = tf32r(__cosf(p) * INV_SQRT_MF);
                kpt[(m + 128) * TSTR + tok] = tf32r(__sinf(p) * INV_SQRT_MF);
            }
        __syncthreads();

#pragma unroll
        for (int ks = 0; ks < 4; ks++) {
            const int kb = ks * 8;
            uint32_t af[2][4], bv2[2][4];
#pragma unroll
            for (int mi = 0; mi < 2; mi++)
                ldsm4(af[mi], smaddr(kpt + (mB0 + mi * 16) * TSTR + kb + aoffT));
#pragma unroll
            for (int nh = 0; nh < 2; nh++)
                ldsm4(bv2[nh], smaddr(vts + (dB0 + nh * 16) * TSTR + kb + boffT));
#pragma unroll
            for (int mi = 0; mi < 2; mi++)
#pragma unroll
                for (int nj = 0; nj < 4; nj++)
                    mma_tf32(kvacc[mi][nj], af[mi], &bv2[nj >> 1][(nj & 1) * 2]);
        }
    }

    float* outp = kvp + ((size_t)split * BB * HH + b * HH + h) * TWO_M * DH;
#pragma unroll
    for (int mi = 0; mi < 2; mi++)
#pragma unroll
        for (int nj = 0; nj < 4; nj++) {
            int m = mB0 + mi * 16 + g;
            int d = dB0 + nj * 8 + 2 * c;
            *(float2*)(outp + m * DH + d) =
                make_float2(kvacc[mi][nj][0], kvacc[mi][nj][1]);
            *(float2*)(outp + (m + 8) * DH + d) =
                make_float2(kvacc[mi][nj][2], kvacc[mi][nj][3]);
        }
}

// ---------------------------------------------------------------------------
__global__ void kv_reduce(const float4* __restrict__ kvp, float4* __restrict__ kv)
{
    const int N4 = BB * HH * TWO_M * DH / 4;
    int i = blockIdx.x * blockDim.x + threadIdx.x;
    if (i >= N4) return;
    float4 s = kvp[i];
#pragma unroll
    for (int sp = 1; sp < KV_SPLIT; sp++) {
        float4 t = kvp[(size_t)sp * N4 + i];
        s.x += t.x; s.y += t.y; s.z += t.z; s.w += t.w;
    }
    kv[i] = s;
}

// ---------------------------------------------------------------------------
// attn: out half[tok,64] = q'[tok,256] @ kv[256,64]. ACH=8. Writes fp16 att.
// ---------------------------------------------------------------------------
#define ACH 8
#define QSTR 260
#define ATTN_SMEM ((128*FSTR + 64*FSTR + 2*64*QSTR) * 4)

__global__ __launch_bounds__(512) void attn_mma(
    const float* __restrict__ Q, const float* __restrict__ kv,
    const float* __restrict__ proj, __half* __restrict__ out)
{
    extern __shared__ float sm[];
    float* projT = sm;
    float* qsh   = projT + 128 * FSTR;
    float* qps   = qsh   + 64 * FSTR;
    float* kvt   = qps   + 64 * QSTR;

    const int h = blockIdx.y, b = blockIdx.z;
    const int tid = threadIdx.x;
    const int warp = tid >> 5, lane = tid & 31;
    const int g = lane >> 2, c = lane & 3;
    const int aoffF = AOFF(lane, FSTR);
    const int boffF = BOFF(lane, FSTR);
    const int aoffQ = AOFF(lane, QSTR);
    const int boffQ = BOFF(lane, QSTR);

    for (int it = tid; it < 2048; it += 512) {
        int d = it >> 5;
        int m4 = (it & 31) * 4;
        float4 pv = *(const float4*)(proj + d * MF + m4);
        projT[(m4 + 0) * FSTR + d] = tf32r(pv.x);
        projT[(m4 + 1) * FSTR + d] = tf32r(pv.y);
        projT[(m4 + 2) * FSTR + d] = tf32r(pv.z);
        projT[(m4 + 3) * FSTR + d] = tf32r(pv.w);
    }
    const float* kvsrc = kv + ((size_t)(b * HH + h)) * TWO_M * DH;
    for (int it = tid; it < 4096; it += 512) {
        int m = it >> 4;
        int d4 = (it & 15) * 4;
        float4 v = *(const float4*)(kvsrc + m * DH + d4);
        kvt[(d4 + 0) * QSTR + m] = tf32r(v.x);
        kvt[(d4 + 1) * QSTR + m] = tf32r(v.y);
        kvt[(d4 + 2) * QSTR + m] = tf32r(v.z);
        kvt[(d4 + 3) * QSTR + m] = tf32r(v.w);
    }

    const int wtokA = (warp & 3) * 16, wmA = (warp >> 2) * 32;
    const int tokB = (warp & 3) * 16, dB = (warp >> 2) * 16;

    for (int cc = 0; cc < ACH; cc++) {
        const int l0 = (blockIdx.x * ACH + cc) * 64;
        __syncthreads();
        for (int it = tid; it < 1024; it += 512) {
            int t = it >> 4;
            int d4 = (it & 15) * 4;
            size_t row = (size_t)(b * LL + l0 + t) * DM + h * DH + d4;
            float4 qv = *(const float4*)(Q + row);
            *(float4*)&qsh[t * FSTR + d4] = make_float4(
                tf32r(qv.x), tf32r(qv.y), tf32r(qv.z), tf32r(qv.w));
        }
        __syncthreads();

        float pacc[4][4];
#pragma unroll
        for (int nj = 0; nj < 4; nj++)
#pragma unroll
            for (int r = 0; r < 4; r++) pacc[nj][r] = 0.f;

#pragma unroll
        for (int ks = 0; ks < 8; ks++) {
            const int kb = ks * 8;
            uint32_t ah[4], bfr[2][4];
            ldsm4(ah, smaddr(qsh + wtokA * FSTR + kb + aoffF));
            ldsm4(bfr[0], smaddr(projT + wmA * FSTR + kb + boffF));
            ldsm4(bfr[1], smaddr(projT + (wmA + 16) * FSTR + kb + boffF));
#pragma unroll
            for (int nj = 0; nj < 4; nj++)
                mma_tf32(pacc[nj], ah, &bfr[nj >> 1][(nj & 1) * 2]);
        }

#pragma unroll
        for (int nj = 0; nj < 4; nj++)
#pragma unroll
            for (int half2i = 0; half2i < 2; half2i++) {
                int tok = wtokA + g + half2i * 8;
                int m0 = wmA + nj * 8 + 2 * c;
                float p0 = pacc[nj][half2i * 2 + 0] * INV_SQRT_DH;
                float p1 = pacc[nj][half2i * 2 + 1] * INV_SQRT_DH;
                *(float2*)&qps[tok * QSTR + m0] = make_float2(
                    tf32r(__cosf(p0) * INV_SQRT_MF), tf32r(__cosf(p1) * INV_SQRT_MF));
                *(float2*)&qps[tok * QSTR + m0 + 128] = make_float2(
                    tf32r(__sinf(p0) * INV_SQRT_MF), tf32r(__sinf(p1) * INV_SQRT_MF));
            }
        __syncthreads();

        float oacc[2][4];
#pragma unroll
        for (int nj = 0; nj < 2; nj++)
#pragma unroll
            for (int r = 0; r < 4; r++) oacc[nj][r] = 0.f;

#pragma unroll
        for (int ks = 0; ks < 32; ks++) {
            const int kb = ks * 8;
            uint32_t af[4], bv2[4];
            ldsm4(af, smaddr(qps + tokB * QSTR + kb + aoffQ));
            ldsm4(bv2, smaddr(kvt + dB * QSTR + kb + boffQ));
#pragma unroll
            for (int nj = 0; nj < 2; nj++)
                mma_tf32(oacc[nj], af, &bv2[nj * 2]);
        }

#pragma unroll
        for (int nj = 0; nj < 2; nj++) {
            int tok = l0 + tokB + g;
            int col = h * DH + dB + nj * 8 + 2 * c;
            __half2 o0 = __floats2half2_rn(oacc[nj][0], oacc[nj][1]);
            __half2 o1 = __floats2half2_rn(oacc[nj][2], oacc[nj][3]);
            *(__half2*)(out + (size_t)(b * LL + tok) * DM + col) = o0;
            *(__half2*)(out + (size_t)(b * LL + tok + 8) * DM + col) = o1;
        }
    }
}

// ---------------------------------------------------------------------------
extern "C" void kernel_launch(void* const* d_in, const int* in_sizes, int n_in,
                              void* d_out, int out_size)
{
    const float* x    = (const float*)d_in[0];
    const float* proj = (const float*)d_in[1];
    const float* Wq   = (const float*)d_in[2];
    const float* bq   = (const float*)d_in[3];
    const float* Wk   = (const float*)d_in[4];
    const float* bk   = (const float*)d_in[5];
    const float* Wv   = (const float*)d_in[6];
    const float* bv   = (const float*)d_in[7];
    const float* Wo   = (const float*)d_in[8];
    const float* bo   = (const float*)d_in[9];
    float* out = (float*)d_out;

    float *q, *k, *v, *kvp, *kvf;
    __half *xh, *ath, *wh;
    cudaGetSymbolAddress((void**)&q,   g_q);
    cudaGetSymbolAddress((void**)&k,   g_k);
    cudaGetSymbolAddress((void**)&v,   g_v);
    cudaGetSymbolAddress((void**)&xh,  g_xh);
    cudaGetSymbolAddress((void**)&ath, g_ath);
    cudaGetSymbolAddress((void**)&wh,  g_wh);
    cudaGetSymbolAddress((void**)&kvp, g_kvp);
    cudaGetSymbolAddress((void**)&kvf, g_kv);

    static cudaStream_t s2 = nullptr;
    static cudaEvent_t evFork = nullptr, evJoin = nullptr;
    static bool init_done = false;
    if (!init_done) {
        cudaFuncSetAttribute(kv_gemm_h, cudaFuncAttributeMaxDynamicSharedMemorySize, GSMEMH);
        cudaFuncSetAttribute(gemm_one_h, cudaFuncAttributeMaxDynamicSharedMemorySize, GSMEMH);
        cudaFuncSetAttribute(feat_kv, cudaFuncAttributeMaxDynamicSharedMemorySize, FEAT_SMEM);
        cudaFuncSetAttribute(attn_mma, cudaFuncAttributeMaxDynamicSharedMemorySize, ATTN_SMEM);
        cudaStreamCreateWithFlags(&s2, cudaStreamNonBlocking);
        cudaEventCreateWithFlags(&evFork, cudaEventDisableTiming);
        cudaEventCreateWithFlags(&evJoin, cudaEventDisableTiming);
        init_done = true;
    }

    // prep: convert x and all 4 W to fp16
    const int XN8 = TT * DM / 8;
    cvt_x_h<<<(XN8 + 255) / 256, 256>>>((const float4*)x, (uint2*)xh, XN8);
    const int WN4ALL = DM * DM;
    cvt_w_h<<<(WN4ALL + 255) / 256, 256>>>(
        (const float4*)Wq, (const float4*)Wk, (const float4*)Wv, (const float4*)Wo,
        (uint2*)wh);

    // fork: Q-projection on s2
    cudaEventRecord(evFork, 0);
    cudaStreamWaitEvent(s2, evFork, 0);
    gemm_one_h<<<dim3(DM / 128, TT / 128), 256, GSMEMH, s2>>>(
        xh, wh + 0 * (size_t)DM * DM, bq, q);
    cudaEventRecord(evJoin, s2);

    kv_gemm_h<<<dim3(DM / 128, TT / 128, 2), 256, GSMEMH>>>(xh, wh, bk, bv, k, v);

    feat_kv<<<dim3(KV_SPLIT, HH, BB), 512, FEAT_SMEM>>>(k, v, proj, kvp);

    const int N4 = BB * HH * TWO_M * DH / 4;
    kv_reduce<<<(N4 + 255) / 256, 256>>>((const float4*)kvp, (float4*)kvf);

    cudaStreamWaitEvent(0, evJoin, 0);

    attn_mma<<<dim3(LL / (64 * ACH), HH, BB), 512, ATTN_SMEM>>>(q, kvf, proj, ath);

    gemm_one_h<<<dim3(DM / 128, TT / 128), 256, GSMEMH>>>(
        ath, wh + 3 * (size_t)DM * DM, bo, out);
}

// round 17
// speedup vs baseline: 1.0379x; 1.0379x over previous
#include <cuda_runtime.h>
#include <math.h>
#include <stdint.h>

#define BB 4
#define LL 4096
#define TT (BB*LL)
#define DM 1024
#define HH 16
#define DH 64
#define MF 128
#define TWO_M 256
#define KV_SPLIT 16
#define LSPLIT (LL/KV_SPLIT)   // 256

#define INV_SQRT_DH 0.125f
#define INV_SQRT_MF 0.08838834764831843f

__device__ float g_q[TT*DM];
__device__ float g_k[TT*DM];
__device__ float g_v[TT*DM];
__device__ float g_att[TT*DM];
__device__ float g_kvp[(size_t)KV_SPLIT*BB*HH*TWO_M*DH];

__device__ __forceinline__ float tf32r(float x) {
    uint32_t u;
    asm("cvt.rna.tf32.f32 %0, %1;" : "=r"(u) : "f"(x));
    return __uint_as_float(u);
}

__device__ __forceinline__ void mma_tf32(float* d, const uint32_t* a, const uint32_t* b) {
    asm volatile(
        "mma.sync.aligned.m16n8k8.row.col.f32.tf32.tf32.f32 "
        "{%0,%1,%2,%3}, {%4,%5,%6,%7}, {%8,%9}, {%0,%1,%2,%3};\n"
        : "+f"(d[0]), "+f"(d[1]), "+f"(d[2]), "+f"(d[3])
        : "r"(a[0]), "r"(a[1]), "r"(a[2]), "r"(a[3]), "r"(b[0]), "r"(b[1]));
}

__device__ __forceinline__ uint32_t smaddr(const void* p) {
    return (uint32_t)__cvta_generic_to_shared(p);
}

__device__ __forceinline__ void ldsm4(uint32_t* r, uint32_t a) {
    asm volatile("ldmatrix.sync.aligned.m8n8.x4.shared.b16 {%0,%1,%2,%3}, [%4];"
                 : "=r"(r[0]), "=r"(r[1]), "=r"(r[2]), "=r"(r[3]) : "r"(a));
}

#define AOFF(lane, STR) (((((lane) >> 3) & 1) * 8 + ((lane) & 7)) * (STR) + ((lane) >> 4) * 4)
#define BOFF(lane, STR) ((((lane) >> 4) * 8 + ((lane) & 7)) * (STR) + (((lane) >> 3) & 1) * 4)

// ---------------------------------------------------------------------------
// GEMM body: C[128,128 tile] = A[M,1024] * W[N,1024]^T + bias
// Raw fp32 operands (mma truncates to tf32). cp.async 3-stage, 2 CTA/SM.
// ---------------------------------------------------------------------------
#define GS 3
#define GSTR 36
#define GSTAGE (128*GSTR)
#define GSMEM (2*GS*GSTAGE*4)

__device__ __forceinline__ void gemm_body(
    const float* __restrict__ A, const float* __restrict__ W,
    const float* __restrict__ bias, float* __restrict__ C)
{
    extern __shared__ float sg[];
    float* As = sg;
    float* Ws = sg + GS * GSTAGE;

    const int tid = threadIdx.x;
    const int bm = blockIdx.y * 128;
    const int bn = blockIdx.x * 128;
    const int warp = tid >> 5, lane = tid & 31;
    const int wm = (warp & 1) * 64;
    const int wn = (warp >> 1) * 32;
    const int g = lane >> 2, c = lane & 3;
    const int aoff = AOFF(lane, GSTR);
    const int boff = BOFF(lane, GSTR);

    float d[4][4][4];
#pragma unroll
    for (int mt = 0; mt < 4; mt++)
#pragma unroll
        for (int nt = 0; nt < 4; nt++)
#pragma unroll
            for (int r = 0; r < 4; r++) d[mt][nt][r] = 0.f;

    auto issue = [&](int st, int k0) {
#pragma unroll
        for (int j = 0; j < 4; j++) {
            int id = tid + j * 256;
            int row = id >> 3, kq = (id & 7) * 4;
            asm volatile("cp.async.cg.shared.global [%0], [%1], 16;\n"
                         :: "r"(smaddr(&As[st * GSTAGE + row * GSTR + kq])),
                            "l"(A + (size_t)(bm + row) * DM + k0 + kq));
            asm volatile("cp.async.cg.shared.global [%0], [%1], 16;\n"
                         :: "r"(smaddr(&Ws[st * GSTAGE + row * GSTR + kq])),
                            "l"(W + (size_t)(bn + row) * DM + k0 + kq));
        }
    };

    issue(0, 0);  asm volatile("cp.async.commit_group;\n");
    issue(1, 32); asm volatile("cp.async.commit_group;\n");

    const int NIT = DM / 32;
    for (int i = 0; i < NIT; i++) {
        asm volatile("cp.async.wait_group 1;\n");
        __syncthreads();
        if (i + 2 < NIT) issue((i + 2) % GS, (i + 2) * 32);
        asm volatile("cp.async.commit_group;\n");

        const float* Ab = As + (i % GS) * GSTAGE;
        const float* Wb = Ws + (i % GS) * GSTAGE;
#pragma unroll
        for (int ks = 0; ks < 4; ks++) {
            const int kb = ks * 8;
            uint32_t a[4][4], bq2[2][4];
#pragma unroll
            for (int mt = 0; mt < 4; mt++)
                ldsm4(a[mt], smaddr(Ab + (wm + mt * 16) * GSTR + kb + aoff));
            ldsm4(bq2[0], smaddr(Wb + wn * GSTR + kb + boff));
            ldsm4(bq2[1], smaddr(Wb + (wn + 16) * GSTR + kb + boff));
#pragma unroll
            for (int mt = 0; mt < 4; mt++)
#pragma unroll
                for (int nt = 0; nt < 4; nt++)
                    mma_tf32(d[mt][nt], a[mt], &bq2[nt >> 1][(nt & 1) * 2]);
        }
    }

#pragma unroll
    for (int nt = 0; nt < 4; nt++) {
        int col = bn + wn + nt * 8 + 2 * c;
        float b0 = bias[col], b1 = bias[col + 1];
#pragma unroll
        for (int mt = 0; mt < 4; mt++) {
            int row = bm + wm + mt * 16 + g;
            *(float2*)(C + (size_t)row * DM + col) =
                make_float2(d[mt][nt][0] + b0, d[mt][nt][1] + b1);
            *(float2*)(C + (size_t)(row + 8) * DM + col) =
                make_float2(d[mt][nt][2] + b0, d[mt][nt][3] + b1);
        }
    }
}

__global__ __launch_bounds__(256, 2) void kv_gemm(
    const float* __restrict__ A,
    const float* __restrict__ Wk, const float* __restrict__ Wv,
    const float* __restrict__ bk, const float* __restrict__ bv,
    float* __restrict__ k, float* __restrict__ v)
{
    int z = blockIdx.z;   // 0 -> K, 1 -> V
    const float* W = (z == 0) ? Wk : Wv;
    const float* bias = (z == 0) ? bk : bv;
    float* C = (z == 0) ? k : v;
    gemm_body(A, W, bias, C);
}

__global__ __launch_bounds__(256, 2) void gemm_one(
    const float* __restrict__ A, const float* __restrict__ W,
    const float* __restrict__ bias, float* __restrict__ C)
{
    gemm_body(A, W, bias, C);
}

// ---------------------------------------------------------------------------
// feat_kv (R13): 32-token chunks, 2 CTAs/SM. 512 threads.
// ---------------------------------------------------------------------------
#define FSTR 68
#define TSTR 36
#define FEAT_SMEM ((128*FSTR + 32*FSTR + 64*TSTR + 256*TSTR) * 4)

__global__ __launch_bounds__(512, 2) void feat_kv(
    const float* __restrict__ Kmat, const float* __restrict__ Vmat,
    const float* __restrict__ proj, float* __restrict__ kvp)
{
    extern __shared__ float sm[];
    float* projT = sm;
    float* ksh   = projT + 128 * FSTR;
    float* vts   = ksh   + 32 * FSTR;
    float* kpt   = vts   + 64 * TSTR;

    const int split = blockIdx.x, h = blockIdx.y, b = blockIdx.z;
    const int tid = threadIdx.x;
    const int warp = tid >> 5, lane = tid & 31;
    const int g = lane >> 2, c = lane & 3;
    const int aoffF = AOFF(lane, FSTR);
    const int boffF = BOFF(lane, FSTR);
    const int aoffT = AOFF(lane, TSTR);
    const int boffT = BOFF(lane, TSTR);

    for (int it = tid; it < 2048; it += 512) {
        int d = it >> 5;
        int m4 = (it & 31) * 4;
        float4 pv = *(const float4*)(proj + d * MF + m4);
        projT[(m4 + 0) * FSTR + d] = tf32r(pv.x);
        projT[(m4 + 1) * FSTR + d] = tf32r(pv.y);
        projT[(m4 + 2) * FSTR + d] = tf32r(pv.z);
        projT[(m4 + 3) * FSTR + d] = tf32r(pv.w);
    }

    const int wtokA = (warp & 1) * 16, wmA = (warp >> 1) * 16;
    const int mB0 = (warp & 7) * 32, dB0 = (warp >> 3) * 32;
    const int l0 = split * LSPLIT;

    float kvacc[2][4][4];
#pragma unroll
    for (int mi = 0; mi < 2; mi++)
#pragma unroll
        for (int nj = 0; nj < 4; nj++)
#pragma unroll
            for (int r = 0; r < 4; r++) kvacc[mi][nj][r] = 0.f;

    for (int ch = 0; ch < LSPLIT; ch += 32) {
        __syncthreads();
        {
            int it = tid;
            int t = it >> 4;
            int d4 = (it & 15) * 4;
            size_t row = (size_t)(b * LL + l0 + ch + t) * DM + h * DH + d4;
            float4 kvv = *(const float4*)(Kmat + row);
            *(float4*)&ksh[t * FSTR + d4] = make_float4(
                tf32r(kvv.x), tf32r(kvv.y), tf32r(kvv.z), tf32r(kvv.w));
            float4 vv = *(const float4*)(Vmat + row);
            vts[(d4 + 0) * TSTR + t] = tf32r(vv.x);
            vts[(d4 + 1) * TSTR + t] = tf32r(vv.y);
            vts[(d4 + 2) * TSTR + t] = tf32r(vv.z);
            vts[(d4 + 3) * TSTR + t] = tf32r(vv.w);
        }
        __syncthreads();

        float pacc[2][4];
#pragma unroll
        for (int nj = 0; nj < 2; nj++)
#pragma unroll
            for (int r = 0; r < 4; r++) pacc[nj][r] = 0.f;

#pragma unroll
        for (int ks = 0; ks < 8; ks++) {
            const int kb = ks * 8;
            uint32_t ah[4], bfr[4];
            ldsm4(ah, smaddr(ksh + wtokA * FSTR + kb + aoffF));
            ldsm4(bfr, smaddr(projT + wmA * FSTR + kb + boffF));
#pragma unroll
            for (int nj = 0; nj < 2; nj++)
                mma_tf32(pacc[nj], ah, &bfr[nj * 2]);
        }

#pragma unroll
        for (int nj = 0; nj < 2; nj++)
#pragma unroll
            for (int r = 0; r < 4; r++) {
                int tok = wtokA + g + (r >> 1) * 8;
                int m = wmA + nj * 8 + 2 * c + (r & 1);
                float p = pacc[nj][r] * INV_SQRT_DH;
                kpt[m * TSTR + tok] = tf32r(__cosf(p) * INV_SQRT_MF);
                kpt[(m + 128) * TSTR + tok] = tf32r(__sinf(p) * INV_SQRT_MF);
            }
        __syncthreads();

#pragma unroll
        for (int ks = 0; ks < 4; ks++) {
            const int kb = ks * 8;
            uint32_t af[2][4], bv2[2][4];
#pragma unroll
            for (int mi = 0; mi < 2; mi++)
                ldsm4(af[mi], smaddr(kpt + (mB0 + mi * 16) * TSTR + kb + aoffT));
#pragma unroll
            for (int nh = 0; nh < 2; nh++)
                ldsm4(bv2[nh], smaddr(vts + (dB0 + nh * 16) * TSTR + kb + boffT));
#pragma unroll
            for (int mi = 0; mi < 2; mi++)
#pragma unroll
                for (int nj = 0; nj < 4; nj++)
                    mma_tf32(kvacc[mi][nj], af[mi], &bv2[nj >> 1][(nj & 1) * 2]);
        }
    }

    float* outp = kvp + ((size_t)split * BB * HH + b * HH + h) * TWO_M * DH;
#pragma unroll
    for (int mi = 0; mi < 2; mi++)
#pragma unroll
        for (int nj = 0; nj < 4; nj++) {
            int m = mB0 + mi * 16 + g;
            int d = dB0 + nj * 8 + 2 * c;
            *(float2*)(outp + m * DH + d) =
                make_float2(kvacc[mi][nj][0], kvacc[mi][nj][1]);
            *(float2*)(outp + (m + 8) * DH + d) =
                make_float2(kvacc[mi][nj][2], kvacc[mi][nj][3]);
        }
}

// ---------------------------------------------------------------------------
// attn: fused kv-partial reduction + feature + matmul. ACH=8. 512 threads.
// ---------------------------------------------------------------------------
#define ACH 8
#define QSTR 260
#define ATTN_SMEM ((128*FSTR + 64*FSTR + 2*64*QSTR) * 4)

__global__ __launch_bounds__(512) void attn_mma(
    const float* __restrict__ Q, const float* __restrict__ kvp,
    const float* __restrict__ proj, float* __restrict__ out)
{
    extern __shared__ float sm[];
    float* projT = sm;
    float* qsh   = projT + 128 * FSTR;
    float* qps   = qsh   + 64 * FSTR;
    float* kvt   = qps   + 64 * QSTR;

    const int h = blockIdx.y, b = blockIdx.z;
    const int tid = threadIdx.x;
    const int warp = tid >> 5, lane = tid & 31;
    const int g = lane >> 2, c = lane & 3;
    const int aoffF = AOFF(lane, FSTR);
    const int boffF = BOFF(lane, FSTR);
    const int aoffQ = AOFF(lane, QSTR);
    const int boffQ = BOFF(lane, QSTR);

    for (int it = tid; it < 2048; it += 512) {
        int d = it >> 5;
        int m4 = (it & 31) * 4;
        float4 pv = *(const float4*)(proj + d * MF + m4);
        projT[(m4 + 0) * FSTR + d] = tf32r(pv.x);
        projT[(m4 + 1) * FSTR + d] = tf32r(pv.y);
        projT[(m4 + 2) * FSTR + d] = tf32r(pv.z);
        projT[(m4 + 3) * FSTR + d] = tf32r(pv.w);
    }
    // fused reduce over KV_SPLIT partials, then transpose into kvt
    const float* kvsrc = kvp + ((size_t)(b * HH + h)) * TWO_M * DH;
    const size_t spstride = (size_t)BB * HH * TWO_M * DH;
    for (int it = tid; it < 4096; it += 512) {
        int m = it >> 4;
        int d4 = (it & 15) * 4;
        float4 s = *(const float4*)(kvsrc + (size_t)m * DH + d4);
#pragma unroll
        for (int sp = 1; sp < KV_SPLIT; sp++) {
            float4 t = *(const float4*)(kvsrc + sp * spstride + (size_t)m * DH + d4);
            s.x += t.x; s.y += t.y; s.z += t.z; s.w += t.w;
        }
        kvt[(d4 + 0) * QSTR + m] = tf32r(s.x);
        kvt[(d4 + 1) * QSTR + m] = tf32r(s.y);
        kvt[(d4 + 2) * QSTR + m] = tf32r(s.z);
        kvt[(d4 + 3) * QSTR + m] = tf32r(s.w);
    }

    const int wtokA = (warp & 3) * 16, wmA = (warp >> 2) * 32;
    const int tokB = (warp & 3) * 16, dB = (warp >> 2) * 16;

    for (int cc = 0; cc < ACH; cc++) {
        const int l0 = (blockIdx.x * ACH + cc) * 64;
        __syncthreads();
        for (int it = tid; it < 1024; it += 512) {
            int t = it >> 4;
            int d4 = (it & 15) * 4;
            size_t row = (size_t)(b * LL + l0 + t) * DM + h * DH + d4;
            float4 qv = *(const float4*)(Q + row);
            *(float4*)&qsh[t * FSTR + d4] = make_float4(
                tf32r(qv.x), tf32r(qv.y), tf32r(qv.z), tf32r(qv.w));
        }
        __syncthreads();

        float pacc[4][4];
#pragma unroll
        for (int nj = 0; nj < 4; nj++)
#pragma unroll
            for (int r = 0; r < 4; r++) pacc[nj][r] = 0.f;

#pragma unroll
        for (int ks = 0; ks < 8; ks++) {
            const int kb = ks * 8;
            uint32_t ah[4], bfr[2][4];
            ldsm4(ah, smaddr(qsh + wtokA * FSTR + kb + aoffF));
            ldsm4(bfr[0], smaddr(projT + wmA * FSTR + kb + boffF));
            ldsm4(bfr[1], smaddr(projT + (wmA + 16) * FSTR + kb + boffF));
#pragma unroll
            for (int nj = 0; nj < 4; nj++)
                mma_tf32(pacc[nj], ah, &bfr[nj >> 1][(nj & 1) * 2]);
        }

#pragma unroll
        for (int nj = 0; nj < 4; nj++)
#pragma unroll
            for (int hv = 0; hv < 2; hv++) {
                int tok = wtokA + g + hv * 8;
                int m0 = wmA + nj * 8 + 2 * c;
                float p0 = pacc[nj][hv * 2 + 0] * INV_SQRT_DH;
                float p1 = pacc[nj][hv * 2 + 1] * INV_SQRT_DH;
                *(float2*)&qps[tok * QSTR + m0] = make_float2(
                    tf32r(__cosf(p0) * INV_SQRT_MF), tf32r(__cosf(p1) * INV_SQRT_MF));
                *(float2*)&qps[tok * QSTR + m0 + 128] = make_float2(
                    tf32r(__sinf(p0) * INV_SQRT_MF), tf32r(__sinf(p1) * INV_SQRT_MF));
            }
        __syncthreads();

        float oacc[2][4];
#pragma unroll
        for (int nj = 0; nj < 2; nj++)
#pragma unroll
            for (int r = 0; r < 4; r++) oacc[nj][r] = 0.f;

#pragma unroll
        for (int ks = 0; ks < 32; ks++) {
            const int kb = ks * 8;
            uint32_t af[4], bv2[4];
            ldsm4(af, smaddr(qps + tokB * QSTR + kb + aoffQ));
            ldsm4(bv2, smaddr(kvt + dB * QSTR + kb + boffQ));
#pragma unroll
            for (int nj = 0; nj < 2; nj++)
                mma_tf32(oacc[nj], af, &bv2[nj * 2]);
        }

#pragma unroll
        for (int nj = 0; nj < 2; nj++) {
            int tok = l0 + tokB + g;
            int col = h * DH + dB + nj * 8 + 2 * c;
            *(float2*)(out + (size_t)(b * LL + tok) * DM + col) =
                make_float2(tf32r(oacc[nj][0]), tf32r(oacc[nj][1]));
            *(float2*)(out + (size_t)(b * LL + tok + 8) * DM + col) =
                make_float2(tf32r(oacc[nj][2]), tf32r(oacc[nj][3]));
        }
    }
}

// ---------------------------------------------------------------------------
extern "C" void kernel_launch(void* const* d_in, const int* in_sizes, int n_in,
                              void* d_out, int out_size)
{
    const float* x    = (const float*)d_in[0];
    const float* proj = (const float*)d_in[1];
    const float* Wq   = (const float*)d_in[2];
    const float* bq   = (const float*)d_in[3];
    const float* Wk   = (const float*)d_in[4];
    const float* bk   = (const float*)d_in[5];
    const float* Wv   = (const float*)d_in[6];
    const float* bv   = (const float*)d_in[7];
    const float* Wo   = (const float*)d_in[8];
    const float* bo   = (const float*)d_in[9];
    float* out = (float*)d_out;

    float *q, *k, *v, *att, *kvp;
    cudaGetSymbolAddress((void**)&q,   g_q);
    cudaGetSymbolAddress((void**)&k,   g_k);
    cudaGetSymbolAddress((void**)&v,   g_v);
    cudaGetSymbolAddress((void**)&att, g_att);
    cudaGetSymbolAddress((void**)&kvp, g_kvp);

    static cudaStream_t s2 = nullptr;
    static cudaEvent_t evFork = nullptr, evJoin = nullptr;
    static bool init_done = false;
    if (!init_done) {
        cudaFuncSetAttribute(kv_gemm, cudaFuncAttributeMaxDynamicSharedMemorySize, GSMEM);
        cudaFuncSetAttribute(gemm_one, cudaFuncAttributeMaxDynamicSharedMemorySize, GSMEM);
        cudaFuncSetAttribute(feat_kv, cudaFuncAttributeMaxDynamicSharedMemorySize, FEAT_SMEM);
        cudaFuncSetAttribute(attn_mma, cudaFuncAttributeMaxDynamicSharedMemorySize, ATTN_SMEM);
        cudaStreamCreateWithFlags(&s2, cudaStreamNonBlocking);
        cudaEventCreateWithFlags(&evFork, cudaEventDisableTiming);
        cudaEventCreateWithFlags(&evJoin, cudaEventDisableTiming);
        init_done = true;
    }

    // fork: Q-projection on s2, concurrent with the K/V + feature chain
    cudaEventRecord(evFork, 0);
    cudaStreamWaitEvent(s2, evFork, 0);
    gemm_one<<<dim3(DM / 128, TT / 128), 256, GSMEM, s2>>>(x, Wq, bq, q);
    cudaEventRecord(evJoin, s2);

    kv_gemm<<<dim3(DM / 128, TT / 128, 2), 256, GSMEM>>>(x, Wk, Wv, bk, bv, k, v);

    feat_kv<<<dim3(KV_SPLIT, HH, BB), 512, FEAT_SMEM>>>(k, v, proj, kvp);

    cudaStreamWaitEvent(0, evJoin, 0);

    attn_mma<<<dim3(LL / (64 * ACH), HH, BB), 512, ATTN_SMEM>>>(q, kvp, proj, att);

    gemm_one<<<dim3(DM / 128, TT / 128), 256, GSMEM>>>(att, Wo, bo, out);
}